// round 7
// baseline (speedup 1.0000x reference)
#include <cuda_runtime.h>

// out_b = Wp (s_b ∘ (Wq X_b)) + X_b,  s_b[c] = sum_n (Wk X_b)[c,n]*(Wv X_b)[c,n]
// B=2, C=64, N=1024.
// K1: per 8-column chunk, fused Wk/Wv/Wq projections (weights via __ldg
//     broadcast, X tile in smem), writes Y (unscaled) + s partials.
// K2: reduce s, scale Y, out = Wp·Ys + X.

#define NCH 128            // chunks per batch (8 columns each)
#define NB1 (2 * NCH)      // 256 blocks

__device__ float g_Y[2 * 64 * 1024];       // unscaled Wq·X
__device__ float g_sPart[2][64][NCH];      // per-chunk s partials

// ---------------------------------------------------------------------------
// K1: 256 blocks x 512 threads. Thread = (channel c, column tn).
// ---------------------------------------------------------------------------
__global__ void __launch_bounds__(512) k_proj(
    const float* __restrict__ x,
    const float* __restrict__ wq, const float* __restrict__ wk,
    const float* __restrict__ wv)
{
    __shared__ __align__(16) float Xt[8][68];     // [n][c], row stride 272B (16B-aligned)

    const int tid = threadIdx.x;
    const int blk = blockIdx.x;
    const int b   = blk >> 7;
    const int ch  = blk & (NCH - 1);
    const int n0  = ch * 8;

    // Stage X chunk transposed: 512 elems, 1/thread, coalesced 32B rows.
    {
        const float* xb = x + b * 65536 + n0;
        int c = tid >> 3, n = tid & 7;
        Xt[n][c] = xb[c * 1024 + n];
    }
    __syncthreads();

    const int tn = tid & 7;        // column in chunk
    const int c  = tid >> 3;       // channel

    const float4* XtR = (const float4*)&Xt[tn][0];
    const float4* wk4 = (const float4*)(wk + c * 64);
    const float4* wv4 = (const float4*)(wv + c * 64);
    const float4* wq4 = (const float4*)(wq + c * 64);

    float aK = 0.f, aV = 0.f, aQ = 0.f;
    #pragma unroll
    for (int j4 = 0; j4 < 16; j4++) {
        float4 x4 = XtR[j4];
        float4 k4 = __ldg(&wk4[j4]);
        float4 v4 = __ldg(&wv4[j4]);
        float4 q4 = __ldg(&wq4[j4]);
        aK += k4.x * x4.x + k4.y * x4.y + k4.z * x4.z + k4.w * x4.w;
        aV += v4.x * x4.x + v4.y * x4.y + v4.z * x4.z + v4.w * x4.w;
        aQ += q4.x * x4.x + q4.y * x4.y + q4.z * x4.z + q4.w * x4.w;
    }

    // Y (unscaled): coalesced 32B per channel row.
    g_Y[b * 65536 + c * 1024 + n0 + tn] = aQ;

    // s partial over this chunk's 8 columns (8-lane groups, fixed order).
    float v = aK * aV;
    v += __shfl_down_sync(0xffffffffu, v, 4, 8);
    v += __shfl_down_sync(0xffffffffu, v, 2, 8);
    v += __shfl_down_sync(0xffffffffu, v, 1, 8);
    if (tn == 0) g_sPart[b][c][ch] = v;
}

// ---------------------------------------------------------------------------
// K2: 256 blocks x 512 threads. Thread = (out-channel o, column tn).
// ---------------------------------------------------------------------------
__global__ void __launch_bounds__(512) k_out(
    const float* __restrict__ x,
    const float* __restrict__ wp,
    float* __restrict__ out)
{
    __shared__ __align__(16) float Ysm[8][68];
    __shared__ float Ss[64];

    const int tid = threadIdx.x;
    const int blk = blockIdx.x;
    const int b   = blk >> 7;
    const int ch  = blk & (NCH - 1);
    const int n0  = ch * 8;

    // Stage Y chunk (coalesced) — independent of the s-reduce below.
    {
        int c = tid >> 3, n = tid & 7;
        Ysm[n][c] = __ldcg(&g_Y[b * 65536 + c * 1024 + n0 + n]);
    }

    // Reduce s: 8 threads/channel, each 16 contiguous floats (4x LDG.128),
    // fixed order -> deterministic.
    {
        const int c2 = tid >> 3, q = tid & 7;
        const float4* sp = (const float4*)&g_sPart[b][c2][q * 16];
        float v = 0.f;
        #pragma unroll
        for (int j = 0; j < 4; j++) {
            float4 s4 = __ldcg(&sp[j]);
            v += s4.x + s4.y + s4.z + s4.w;
        }
        v += __shfl_down_sync(0xffffffffu, v, 4, 8);
        v += __shfl_down_sync(0xffffffffu, v, 2, 8);
        v += __shfl_down_sync(0xffffffffu, v, 1, 8);
        if (q == 0) Ss[c2] = v;
    }
    __syncthreads();

    // Scale Y in place (1 elem/thread).
    {
        int c = tid >> 3, n = tid & 7;
        Ysm[n][c] *= Ss[c];
    }
    __syncthreads();

    const int tn = tid & 7;
    const int o  = tid >> 3;

    const float4* YsR = (const float4*)&Ysm[tn][0];
    const float4* wp4 = (const float4*)(wp + o * 64);

    float acc = 0.f;
    #pragma unroll
    for (int j4 = 0; j4 < 16; j4++) {
        float4 y4 = YsR[j4];
        float4 p4 = __ldg(&wp4[j4]);
        acc += p4.x * y4.x + p4.y * y4.y + p4.z * y4.z + p4.w * y4.w;
    }

    const int idx = b * 65536 + o * 1024 + n0 + tn;
    out[idx] = acc + __ldg(&x[idx]);
}

extern "C" void kernel_launch(void* const* d_in, const int* in_sizes, int n_in,
                              void* d_out, int out_size) {
    const float* x  = (const float*)d_in[0];
    const float* wq = (const float*)d_in[1];
    const float* wk = (const float*)d_in[2];
    const float* wv = (const float*)d_in[3];
    const float* wp = (const float*)d_in[4];

    k_proj<<<NB1, 512>>>(x, wq, wk, wv);
    k_out <<<NB1, 512>>>(x, wp, (float*)d_out);
}

// round 8
// speedup vs baseline: 1.2442x; 1.2442x over previous
#include <cuda_runtime.h>

// out_b = Wp (s_b ∘ (Wq X_b)) + X_b,  s_b[c] = sum_n (Wk X_b)[c,n]*(Wv X_b)[c,n]
// B=2, C=64, N=1024. 128 blocks x 256 threads, one wave, ONE grid barrier.
// Block owns 16 spatial columns. Thread tile: 2 channels x 2 columns (cols nt, nt+8).

#define NBLK 128
#define NTHR 256
#define WS 68                 // padded row stride (floats) for weights
#define XS 68                 // padded row stride for Xs/Ys rows

// smem layout (floats)
#define OFF_WK 0
#define OFF_WV (64 * WS)
#define OFF_WQ (2 * 64 * WS)
#define OFF_WP (3 * 64 * WS)
#define OFF_XT (4 * 64 * WS)            // Xs[16][XS]  ([n][j])
#define OFF_YS (OFF_XT + 16 * XS)       // Ys[16][XS]  ([n][j])
#define OFF_SS (OFF_YS + 16 * XS)       // Ss[64]
#define SMEM_FLOATS (OFF_SS + 64)

__device__ float g_sPart[2][64][64];    // [batch][channel][chunk]

// Replay-safe grid barrier (monotonic flag; counter reset before release).
__device__ unsigned g_cnt;
__device__ volatile unsigned g_flag;

__device__ __forceinline__ void gridbar() {
    __syncthreads();
    if (threadIdx.x == 0) {
        unsigned f0 = g_flag;
        __threadfence();
        unsigned old = atomicAdd(&g_cnt, 1u);
        if (old == NBLK - 1) {
            g_cnt = 0;
            __threadfence();
            atomicAdd((unsigned*)&g_flag, 1u);
        } else {
            while (g_flag == f0) { }
        }
        __threadfence();
    }
    __syncthreads();
}

__device__ __forceinline__ float dot4(float4 a, float4 b) {
    return a.x * b.x + a.y * b.y + a.z * b.z + a.w * b.w;
}

extern __shared__ float sm[];

__global__ void __launch_bounds__(NTHR) attn_fused(
    const float* __restrict__ x,
    const float* __restrict__ wq, const float* __restrict__ wk,
    const float* __restrict__ wv, const float* __restrict__ wp,
    float* __restrict__ out)
{
    const int tid = threadIdx.x;
    const int blk = blockIdx.x;
    const int b   = blk >> 6;
    const int ch  = blk & 63;
    const int n0  = ch * 16;

    const int nt = tid & 7;               // column pair: cols nt, nt+8
    const int c0 = (tid >> 3) * 2;        // channel pair

    float* Xs = sm + OFF_XT;
    float* Ys = sm + OFF_YS;
    float* Ss = sm + OFF_SS;

    // ---- Stage all 4 weight matrices (padded rows) + X chunk ---------------
    {
        const float* srcs[4] = {wk, wv, wq, wp};
        #pragma unroll
        for (int i = 0; i < 16; i++) {
            const int e  = tid + NTHR * i;        // 0..4095 float4 index
            const int m  = i >> 2;                // matrix (aligned: 256*4 = 1024)
            const int e2 = e & 1023;              // float4 within matrix
            const int r  = e2 >> 4, c4 = e2 & 15;
            float4 v = ((const float4*)srcs[m])[e2];
            *(float4*)&sm[m * 64 * WS + r * WS + c4 * 4] = v;
        }
        const float* xb = x + b * 65536 + n0;
        #pragma unroll
        for (int i = 0; i < 4; i++) {
            const int e = tid + NTHR * i;         // e = c*16 + n
            Xs[(e & 15) * XS + (e >> 4)] = xb[(e >> 4) * 1024 + (e & 15)];
        }
    }
    __syncthreads();

    // ---- Fused K/V/Q projections, 2ch x 2col register tile -----------------
    {
        const float4* Wk0 = (const float4*)&sm[OFF_WK + c0 * WS];
        const float4* Wk1 = (const float4*)&sm[OFF_WK + (c0 + 1) * WS];
        const float4* Wv0 = (const float4*)&sm[OFF_WV + c0 * WS];
        const float4* Wv1 = (const float4*)&sm[OFF_WV + (c0 + 1) * WS];
        const float4* Wq0 = (const float4*)&sm[OFF_WQ + c0 * WS];
        const float4* Wq1 = (const float4*)&sm[OFF_WQ + (c0 + 1) * WS];
        const float4* X0  = (const float4*)&Xs[nt * XS];
        const float4* X1  = (const float4*)&Xs[(nt + 8) * XS];

        float k00 = 0.f, k01 = 0.f, k10 = 0.f, k11 = 0.f;
        float v00 = 0.f, v01 = 0.f, v10 = 0.f, v11 = 0.f;
        float q00 = 0.f, q01 = 0.f, q10 = 0.f, q11 = 0.f;

        #pragma unroll
        for (int jg = 0; jg < 16; jg++) {
            float4 x0 = X0[jg], x1 = X1[jg];
            float4 kk0 = Wk0[jg], kk1 = Wk1[jg];
            float4 vv0 = Wv0[jg], vv1 = Wv1[jg];
            float4 qq0 = Wq0[jg], qq1 = Wq1[jg];
            k00 += dot4(kk0, x0); k01 += dot4(kk0, x1);
            k10 += dot4(kk1, x0); k11 += dot4(kk1, x1);
            v00 += dot4(vv0, x0); v01 += dot4(vv0, x1);
            v10 += dot4(vv1, x0); v11 += dot4(vv1, x1);
            q00 += dot4(qq0, x0); q01 += dot4(qq0, x1);
            q10 += dot4(qq1, x0); q11 += dot4(qq1, x1);
        }

        // Unscaled Y into smem ([n][c], float2 per row).
        *(float2*)&Ys[nt * XS + c0]       = make_float2(q00, q10);
        *(float2*)&Ys[(nt + 8) * XS + c0] = make_float2(q01, q11);

        // s partials: per channel, sum K*V over this thread's 2 cols, then
        // reduce over the 8-lane column group (fixed order).
        float s0 = k00 * v00 + k01 * v01;
        float s1 = k10 * v10 + k11 * v11;
        s0 += __shfl_down_sync(0xffffffffu, s0, 4, 8);
        s1 += __shfl_down_sync(0xffffffffu, s1, 4, 8);
        s0 += __shfl_down_sync(0xffffffffu, s0, 2, 8);
        s1 += __shfl_down_sync(0xffffffffu, s1, 2, 8);
        s0 += __shfl_down_sync(0xffffffffu, s0, 1, 8);
        s1 += __shfl_down_sync(0xffffffffu, s1, 1, 8);
        if (nt == 0) {
            g_sPart[b][c0][ch]     = s0;
            g_sPart[b][c0 + 1][ch] = s1;
        }
    }

    gridbar();

    // ---- Reduce s (4 threads/channel, fixed order -> deterministic) --------
    {
        const int c = tid >> 2, q = tid & 3;
        const float4* sp = (const float4*)&g_sPart[b][c][q * 16];
        float v = 0.f;
        #pragma unroll
        for (int j = 0; j < 4; j++) {
            float4 s4 = __ldcg(&sp[j]);
            v += s4.x + s4.y + s4.z + s4.w;
        }
        v += __shfl_down_sync(0xffffffffu, v, 2, 4);
        v += __shfl_down_sync(0xffffffffu, v, 1, 4);
        if (q == 0) Ss[c] = v;
    }
    __syncthreads();

    // ---- out = Wp · (s ∘ Ys) + X  (s folded into the GEMM) -----------------
    {
        const float4* Wp0 = (const float4*)&sm[OFF_WP + c0 * WS];
        const float4* Wp1 = (const float4*)&sm[OFF_WP + (c0 + 1) * WS];
        const float4* Y0  = (const float4*)&Ys[nt * XS];
        const float4* Y1  = (const float4*)&Ys[(nt + 8) * XS];
        const float4* S4  = (const float4*)Ss;

        float o00 = 0.f, o01 = 0.f, o10 = 0.f, o11 = 0.f;
        #pragma unroll
        for (int jg = 0; jg < 16; jg++) {
            float4 ss = S4[jg];
            float4 y0 = Y0[jg], y1 = Y1[jg];
            y0.x *= ss.x; y0.y *= ss.y; y0.z *= ss.z; y0.w *= ss.w;
            y1.x *= ss.x; y1.y *= ss.y; y1.z *= ss.z; y1.w *= ss.w;
            float4 p0 = Wp0[jg], p1 = Wp1[jg];
            o00 += dot4(p0, y0); o01 += dot4(p0, y1);
            o10 += dot4(p1, y0); o11 += dot4(p1, y1);
        }
        float* ob = out + b * 65536 + n0;
        ob[c0 * 1024 + nt]           = o00 + Xs[nt * XS + c0];
        ob[c0 * 1024 + nt + 8]       = o01 + Xs[(nt + 8) * XS + c0];
        ob[(c0 + 1) * 1024 + nt]     = o10 + Xs[nt * XS + c0 + 1];
        ob[(c0 + 1) * 1024 + nt + 8] = o11 + Xs[(nt + 8) * XS + c0 + 1];
    }
}

extern "C" void kernel_launch(void* const* d_in, const int* in_sizes, int n_in,
                              void* d_out, int out_size) {
    const float* x  = (const float*)d_in[0];
    const float* wq = (const float*)d_in[1];
    const float* wk = (const float*)d_in[2];
    const float* wv = (const float*)d_in[3];
    const float* wp = (const float*)d_in[4];

    cudaFuncSetAttribute(attn_fused, cudaFuncAttributeMaxDynamicSharedMemorySize,
                         SMEM_FLOATS * (int)sizeof(float));
    attn_fused<<<NBLK, NTHR, SMEM_FLOATS * sizeof(float)>>>(
        x, wq, wk, wv, wp, (float*)d_out);
}

// round 9
// speedup vs baseline: 1.3417x; 1.0784x over previous
#include <cuda_runtime.h>

// out_b = Wp (s_b ∘ (Wq X_b)) + X_b,  s_b[c] = sum_n (Wk X_b)[c,n]*(Wv X_b)[c,n]
// B=2, C=64, N=1024. 128 blocks x 256 threads, one wave, ONE grid barrier.
// Thread tile: 2 channels x 2 columns. Inner products use packed fma.rn.f32x2
// (reduction dim is contiguous in smem -> no packing ops needed).

#define NBLK 128
#define NTHR 256
#define WS 68
#define XS 68

#define OFF_WK 0
#define OFF_WV (64 * WS)
#define OFF_WQ (2 * 64 * WS)
#define OFF_WP (3 * 64 * WS)
#define OFF_XT (4 * 64 * WS)
#define OFF_YS (OFF_XT + 16 * XS)
#define OFF_SS (OFF_YS + 16 * XS)
#define SMEM_FLOATS (OFF_SS + 64)

typedef unsigned long long u64;

__device__ float g_sPart[2][64][64];

__device__ unsigned g_cnt;
__device__ volatile unsigned g_flag;

__device__ __forceinline__ void gridbar() {
    __syncthreads();
    if (threadIdx.x == 0) {
        unsigned f0 = g_flag;
        __threadfence();
        unsigned old = atomicAdd(&g_cnt, 1u);
        if (old == NBLK - 1) {
            g_cnt = 0;
            __threadfence();
            atomicAdd((unsigned*)&g_flag, 1u);
        } else {
            while (g_flag == f0) { }
        }
        __threadfence();
    }
    __syncthreads();
}

__device__ __forceinline__ void fma2(u64& d, u64 a, u64 b) {
    asm("fma.rn.f32x2 %0, %1, %2, %0;" : "+l"(d) : "l"(a), "l"(b));
}
__device__ __forceinline__ u64 mul2(u64 a, u64 b) {
    u64 d;
    asm("mul.rn.f32x2 %0, %1, %2;" : "=l"(d) : "l"(a), "l"(b));
    return d;
}
__device__ __forceinline__ float hsum2(u64 v) {
    float lo, hi;
    asm("mov.b64 {%0, %1}, %2;" : "=f"(lo), "=f"(hi) : "l"(v));
    return lo + hi;
}

extern __shared__ float sm[];

__global__ void __launch_bounds__(NTHR) attn_fused(
    const float* __restrict__ x,
    const float* __restrict__ wq, const float* __restrict__ wk,
    const float* __restrict__ wv, const float* __restrict__ wp,
    float* __restrict__ out)
{
    const int tid = threadIdx.x;
    const int blk = blockIdx.x;
    const int b   = blk >> 6;
    const int ch  = blk & 63;
    const int n0  = ch * 16;

    const int nt = tid & 7;               // column pair: cols nt, nt+8
    const int c0 = (tid >> 3) * 2;        // channel pair

    float* Xs = sm + OFF_XT;
    float* Ys = sm + OFF_YS;
    float* Ss = sm + OFF_SS;

    // ---- Stage weights (padded rows) + X chunk -----------------------------
    {
        const float* srcs[4] = {wk, wv, wq, wp};
        #pragma unroll
        for (int i = 0; i < 16; i++) {
            const int e  = tid + NTHR * i;
            const int m  = i >> 2;
            const int e2 = e & 1023;
            const int r  = e2 >> 4, c4 = e2 & 15;
            float4 v = ((const float4*)srcs[m])[e2];
            *(float4*)&sm[m * 64 * WS + r * WS + c4 * 4] = v;
        }
        const float* xb = x + b * 65536 + n0;
        #pragma unroll
        for (int i = 0; i < 4; i++) {
            const int e = tid + NTHR * i;
            Xs[(e & 15) * XS + (e >> 4)] = xb[(e >> 4) * 1024 + (e & 15)];
        }
    }
    __syncthreads();

    // ---- Fused K/V/Q projections (packed f32x2 along j) --------------------
    {
        const ulonglong2* Wk0 = (const ulonglong2*)&sm[OFF_WK + c0 * WS];
        const ulonglong2* Wk1 = (const ulonglong2*)&sm[OFF_WK + (c0 + 1) * WS];
        const ulonglong2* Wv0 = (const ulonglong2*)&sm[OFF_WV + c0 * WS];
        const ulonglong2* Wv1 = (const ulonglong2*)&sm[OFF_WV + (c0 + 1) * WS];
        const ulonglong2* Wq0 = (const ulonglong2*)&sm[OFF_WQ + c0 * WS];
        const ulonglong2* Wq1 = (const ulonglong2*)&sm[OFF_WQ + (c0 + 1) * WS];
        const ulonglong2* X0  = (const ulonglong2*)&Xs[nt * XS];
        const ulonglong2* X1  = (const ulonglong2*)&Xs[(nt + 8) * XS];

        u64 K00 = 0, K01 = 0, K10 = 0, K11 = 0;
        u64 V00 = 0, V01 = 0, V10 = 0, V11 = 0;
        u64 Q00 = 0, Q01 = 0, Q10 = 0, Q11 = 0;

        #pragma unroll
        for (int jg = 0; jg < 16; jg++) {
            ulonglong2 xa = X0[jg], xb2 = X1[jg];
            ulonglong2 w;
            w = Wk0[jg];
            fma2(K00, w.x, xa.x);  fma2(K00, w.y, xa.y);
            fma2(K01, w.x, xb2.x); fma2(K01, w.y, xb2.y);
            w = Wk1[jg];
            fma2(K10, w.x, xa.x);  fma2(K10, w.y, xa.y);
            fma2(K11, w.x, xb2.x); fma2(K11, w.y, xb2.y);
            w = Wv0[jg];
            fma2(V00, w.x, xa.x);  fma2(V00, w.y, xa.y);
            fma2(V01, w.x, xb2.x); fma2(V01, w.y, xb2.y);
            w = Wv1[jg];
            fma2(V10, w.x, xa.x);  fma2(V10, w.y, xa.y);
            fma2(V11, w.x, xb2.x); fma2(V11, w.y, xb2.y);
            w = Wq0[jg];
            fma2(Q00, w.x, xa.x);  fma2(Q00, w.y, xa.y);
            fma2(Q01, w.x, xb2.x); fma2(Q01, w.y, xb2.y);
            w = Wq1[jg];
            fma2(Q10, w.x, xa.x);  fma2(Q10, w.y, xa.y);
            fma2(Q11, w.x, xb2.x); fma2(Q11, w.y, xb2.y);
        }

        float k00 = hsum2(K00), k01 = hsum2(K01), k10 = hsum2(K10), k11 = hsum2(K11);
        float v00 = hsum2(V00), v01 = hsum2(V01), v10 = hsum2(V10), v11 = hsum2(V11);

        // Unscaled Y into smem ([n][c]).
        *(float2*)&Ys[nt * XS + c0]       = make_float2(hsum2(Q00), hsum2(Q10));
        *(float2*)&Ys[(nt + 8) * XS + c0] = make_float2(hsum2(Q01), hsum2(Q11));

        float s0 = k00 * v00 + k01 * v01;
        float s1 = k10 * v10 + k11 * v11;
        s0 += __shfl_down_sync(0xffffffffu, s0, 4, 8);
        s1 += __shfl_down_sync(0xffffffffu, s1, 4, 8);
        s0 += __shfl_down_sync(0xffffffffu, s0, 2, 8);
        s1 += __shfl_down_sync(0xffffffffu, s1, 2, 8);
        s0 += __shfl_down_sync(0xffffffffu, s0, 1, 8);
        s1 += __shfl_down_sync(0xffffffffu, s1, 1, 8);
        if (nt == 0) {
            g_sPart[b][c0][ch]     = s0;
            g_sPart[b][c0 + 1][ch] = s1;
        }
    }

    gridbar();

    // ---- Reduce s (4 threads/channel, fixed order) -------------------------
    {
        const int c = tid >> 2, q = tid & 3;
        const float4* sp = (const float4*)&g_sPart[b][c][q * 16];
        float v = 0.f;
        #pragma unroll
        for (int j = 0; j < 4; j++) {
            float4 s4 = __ldcg(&sp[j]);
            v += s4.x + s4.y + s4.z + s4.w;
        }
        v += __shfl_down_sync(0xffffffffu, v, 2, 4);
        v += __shfl_down_sync(0xffffffffu, v, 1, 4);
        if (q == 0) Ss[c] = v;
    }
    __syncthreads();

    // ---- out = Wp · (s ∘ Ys) + X  (packed f32x2) ---------------------------
    {
        const ulonglong2* Wp0 = (const ulonglong2*)&sm[OFF_WP + c0 * WS];
        const ulonglong2* Wp1 = (const ulonglong2*)&sm[OFF_WP + (c0 + 1) * WS];
        const ulonglong2* Y0  = (const ulonglong2*)&Ys[nt * XS];
        const ulonglong2* Y1  = (const ulonglong2*)&Ys[(nt + 8) * XS];
        const ulonglong2* S2  = (const ulonglong2*)Ss;

        u64 O00 = 0, O01 = 0, O10 = 0, O11 = 0;
        #pragma unroll
        for (int jg = 0; jg < 16; jg++) {
            ulonglong2 ss = S2[jg];
            ulonglong2 y0 = Y0[jg], y1 = Y1[jg];
            y0.x = mul2(y0.x, ss.x); y0.y = mul2(y0.y, ss.y);
            y1.x = mul2(y1.x, ss.x); y1.y = mul2(y1.y, ss.y);
            ulonglong2 w;
            w = Wp0[jg];
            fma2(O00, w.x, y0.x); fma2(O00, w.y, y0.y);
            fma2(O01, w.x, y1.x); fma2(O01, w.y, y1.y);
            w = Wp1[jg];
            fma2(O10, w.x, y0.x); fma2(O10, w.y, y0.y);
            fma2(O11, w.x, y1.x); fma2(O11, w.y, y1.y);
        }
        float* ob = out + b * 65536 + n0;
        ob[c0 * 1024 + nt]           = hsum2(O00) + Xs[nt * XS + c0];
        ob[c0 * 1024 + nt + 8]       = hsum2(O01) + Xs[(nt + 8) * XS + c0];
        ob[(c0 + 1) * 1024 + nt]     = hsum2(O10) + Xs[nt * XS + c0 + 1];
        ob[(c0 + 1) * 1024 + nt + 8] = hsum2(O11) + Xs[(nt + 8) * XS + c0 + 1];
    }
}

extern "C" void kernel_launch(void* const* d_in, const int* in_sizes, int n_in,
                              void* d_out, int out_size) {
    const float* x  = (const float*)d_in[0];
    const float* wq = (const float*)d_in[1];
    const float* wk = (const float*)d_in[2];
    const float* wv = (const float*)d_in[3];
    const float* wp = (const float*)d_in[4];

    static int smem_set = 0;
    if (!smem_set) {
        cudaFuncSetAttribute(attn_fused, cudaFuncAttributeMaxDynamicSharedMemorySize,
                             SMEM_FLOATS * (int)sizeof(float));
        smem_set = 1;
    }
    attn_fused<<<NBLK, NTHR, SMEM_FLOATS * sizeof(float)>>>(
        x, wq, wk, wv, wp, (float*)d_out);
}